// round 8
// baseline (speedup 1.0000x reference)
#include <cuda_runtime.h>
#include <math.h>

#define EMB 64
#define NLAYERS 2
#define NUx 100000
#define NIx 50000
#define ERx 1000000
#define ETx 800000
#define EPx 200000
#define HALL 192   // EMB*(1+L)

// ---------------- static scratch (no allocations allowed) ----------------
__device__ float g_hu_all[(size_t)NUx * HALL];
__device__ float g_hi_all[(size_t)NIx * HALL];
__device__ float g_fsU_rate[(size_t)NUx * EMB];
__device__ float g_fdU_rb[(size_t)NUx * EMB];
__device__ float g_fsU_tr[(size_t)NUx * EMB];
__device__ float g_fdU_tr[(size_t)NUx * EMB];
__device__ float g_fdI_rate[(size_t)NIx * EMB];
__device__ float g_fsI_rb[(size_t)NIx * EMB];
__device__ float g_p[(size_t)NUx * EMB];
__device__ float g_q[(size_t)NUx * EMB];
__device__ float g_zinf[NUx];
__device__ float g_zint[NUx];
__device__ float g_gate[264];
__device__ float g_sums[4];
__device__ int g_deg[NUx];
__device__ int g_cursor[NUx];
__device__ int g_bsum[64];
__device__ int g_off_item[NIx + 1];
__device__ int g_off_urate[NUx + 1];
__device__ int g_off_trust[NUx + 1];
__device__ int g_val_item[ERx];
__device__ int g_val_urate[ERx];
__device__ int g_val_trust[ETx];

// ---------------- job descriptors ----------------
struct GJob { const float* W; const float* B; float* Y; };
struct GJobs { GJob j[4]; int m; };

struct GatJob {
    const int* off; const int* val; const float* fs; const float* fd;
    const float* attn; const float* bias; const float* resid; int rstride;
    float* out; int ostride; int n;
};
struct GatJobs { GatJob j[3]; int n0, n01, ntot; };

// ---------------- kernels ----------------

__global__ void copy_block(const float* __restrict__ src, float* __restrict__ dst,
                           int dstride, int n64) {
    int i = blockIdx.x * blockDim.x + threadIdx.x;
    if (i >= n64) return;
    int row = i >> 6, j = i & 63;
    dst[(size_t)row * dstride + j] = src[i];
}

// ---- CSR build ----
__global__ void count_kernel(const int* __restrict__ grp, int* __restrict__ deg, int E) {
    int e = blockIdx.x * blockDim.x + threadIdx.x;
    if (e < E) atomicAdd(deg + grp[e], 1);
}

__global__ void scan_bsums(const int* __restrict__ deg, int n, int* __restrict__ bsum) {
    __shared__ int sh[256];
    int t = threadIdx.x;
    int base = blockIdx.x * 4096;
    int s = 0;
#pragma unroll
    for (int i = 0; i < 16; i++) {
        int idx = base + i * 256 + t;
        if (idx < n) s += deg[idx];
    }
    sh[t] = s;
    __syncthreads();
    for (int st = 128; st; st >>= 1) {
        if (t < st) sh[t] += sh[t + st];
        __syncthreads();
    }
    if (t == 0) bsum[blockIdx.x] = sh[0];
}

__global__ void scan_tops(int* __restrict__ bsum, int nb, int* __restrict__ total) {
    __shared__ int sh[64];
    int t = threadIdx.x;   // 64 threads
    int v = (t < nb) ? bsum[t] : 0;
    sh[t] = v;
    __syncthreads();
    for (int st = 1; st < 64; st <<= 1) {
        int x = (t >= st) ? sh[t - st] : 0;
        __syncthreads();
        sh[t] += x;
        __syncthreads();
    }
    if (t < nb) bsum[t] = sh[t] - v;     // exclusive
    if (t == 63) *total = sh[63];
}

__global__ void scan_final(const int* __restrict__ deg, int n,
                           const int* __restrict__ bsum, int* __restrict__ off) {
    __shared__ int sh[256];
    int t = threadIdx.x;
    int base = blockIdx.x * 4096 + t * 16;
    int local[16];
    int s = 0;
#pragma unroll
    for (int i = 0; i < 16; i++) {
        int idx = base + i;
        int d = (idx < n) ? deg[idx] : 0;
        local[i] = d;
        s += d;
    }
    sh[t] = s;
    __syncthreads();
    int v = s;
    for (int st = 1; st < 256; st <<= 1) {
        int x = (t >= st) ? sh[t - st] : 0;
        __syncthreads();
        sh[t] += x;
        __syncthreads();
    }
    int run = bsum[blockIdx.x] + sh[t] - v;
#pragma unroll
    for (int i = 0; i < 16; i++) {
        int idx = base + i;
        if (idx < n) off[idx] = run;
        run += local[i];
    }
}

__global__ void scatter_kernel(const int* __restrict__ grp, const int* __restrict__ other,
                               int E, const int* __restrict__ off,
                               int* __restrict__ cursor, int* __restrict__ val) {
    int e = blockIdx.x * blockDim.x + threadIdx.x;
    if (e >= E) return;
    int d = grp[e];
    int pos = off[d] + atomicAdd(cursor + d, 1);
    val[pos] = other[e];
}

// ---- batched GEMM: 128 threads, 64-row tile, 4 rows x 8 cols per thread ----
// W reads are ty-independent -> warp-broadcast (1 crossbar cycle per LDS.128).
__global__ void gemm64_multi(const float* __restrict__ X, int xstride, int n, GJobs jobs) {
    __shared__ float sW[4096];
    __shared__ float sXT[64 * 68];
    int tx = threadIdx.x;            // 128 threads
    int row0 = blockIdx.x * 64;

    // transpose X tile into sXT (thread: row r, 32 cols)
    {
        int r = tx & 63, qu = tx >> 6;   // qu 0..1 -> cols 32qu..32qu+31
        int row = row0 + r;
        if (row < n) {
            const float4* xr = (const float4*)(X + (size_t)row * xstride);
#pragma unroll
            for (int j = 0; j < 8; j++) {
                float4 v = xr[qu * 8 + j];
                int k = qu * 32 + j * 4;
                sXT[(k + 0) * 68 + r] = v.x;
                sXT[(k + 1) * 68 + r] = v.y;
                sXT[(k + 2) * 68 + r] = v.z;
                sXT[(k + 3) * 68 + r] = v.w;
            }
        } else {
#pragma unroll
            for (int j = 0; j < 8; j++) {
                int k = qu * 32 + j * 4;
                sXT[(k + 0) * 68 + r] = 0.f;
                sXT[(k + 1) * 68 + r] = 0.f;
                sXT[(k + 2) * 68 + r] = 0.f;
                sXT[(k + 3) * 68 + r] = 0.f;
            }
        }
    }
    for (int i = tx; i < 1024; i += 128)
        ((float4*)sW)[i] = ((const float4*)jobs.j[0].W)[i];
    __syncthreads();

    int ty = tx >> 3;    // 0..15 -> rows 4ty..4ty+3
    int c  = tx & 7;     // 0..7  -> cols 8c..8c+7
    int rbase = row0 + 4 * ty;

    for (int m = 0; m < jobs.m; m++) {
        const float* Bm; float* Ym;
        switch (m) {
            case 0: Bm = jobs.j[0].B; Ym = jobs.j[0].Y; break;
            case 1: Bm = jobs.j[1].B; Ym = jobs.j[1].Y; break;
            case 2: Bm = jobs.j[2].B; Ym = jobs.j[2].Y; break;
            default: Bm = jobs.j[3].B; Ym = jobs.j[3].Y; break;
        }
        if (m > 0) {
            const float* Wm;
            switch (m) {
                case 1: Wm = jobs.j[1].W; break;
                case 2: Wm = jobs.j[2].W; break;
                default: Wm = jobs.j[3].W; break;
            }
            __syncthreads();
            for (int i = tx; i < 1024; i += 128)
                ((float4*)sW)[i] = ((const float4*)Wm)[i];
            __syncthreads();
        }

        float4 b0 = *(const float4*)(Bm + 8 * c);
        float4 b1 = *(const float4*)(Bm + 8 * c + 4);
        unsigned long long bp[4];
        asm("mov.b64 %0, {%1,%2};" : "=l"(bp[0]) : "f"(b0.x), "f"(b0.y));
        asm("mov.b64 %0, {%1,%2};" : "=l"(bp[1]) : "f"(b0.z), "f"(b0.w));
        asm("mov.b64 %0, {%1,%2};" : "=l"(bp[2]) : "f"(b1.x), "f"(b1.y));
        asm("mov.b64 %0, {%1,%2};" : "=l"(bp[3]) : "f"(b1.z), "f"(b1.w));
        unsigned long long acc[4][4];
#pragma unroll
        for (int r = 0; r < 4; r++)
#pragma unroll
            for (int q = 0; q < 4; q++) acc[r][q] = bp[q];

#pragma unroll
        for (int k = 0; k < 64; k++) {
            const ulonglong2* wrow = (const ulonglong2*)(sW + k * 64 + 8 * c);
            ulonglong2 w0 = wrow[0];   // cols 8c..8c+3
            ulonglong2 w1 = wrow[1];   // cols 8c+4..8c+7
            float4 a4 = *(const float4*)(sXT + k * 68 + 4 * ty);
            unsigned long long pa[4];
            asm("mov.b64 %0, {%1,%1};" : "=l"(pa[0]) : "f"(a4.x));
            asm("mov.b64 %0, {%1,%1};" : "=l"(pa[1]) : "f"(a4.y));
            asm("mov.b64 %0, {%1,%1};" : "=l"(pa[2]) : "f"(a4.z));
            asm("mov.b64 %0, {%1,%1};" : "=l"(pa[3]) : "f"(a4.w));
#pragma unroll
            for (int r = 0; r < 4; r++) {
                asm("fma.rn.f32x2 %0, %1, %2, %0;" : "+l"(acc[r][0]) : "l"(pa[r]), "l"(w0.x));
                asm("fma.rn.f32x2 %0, %1, %2, %0;" : "+l"(acc[r][1]) : "l"(pa[r]), "l"(w0.y));
                asm("fma.rn.f32x2 %0, %1, %2, %0;" : "+l"(acc[r][2]) : "l"(pa[r]), "l"(w1.x));
                asm("fma.rn.f32x2 %0, %1, %2, %0;" : "+l"(acc[r][3]) : "l"(pa[r]), "l"(w1.y));
            }
        }
#pragma unroll
        for (int r = 0; r < 4; r++) {
            if (rbase + r < n) {
                float* yp = Ym + (size_t)(rbase + r) * 64 + 8 * c;
                *(ulonglong2*)yp       = make_ulonglong2(acc[r][0], acc[r][1]);
                *(ulonglong2*)(yp + 4) = make_ulonglong2(acc[r][2], acc[r][3]);
            }
        }
    }
}

// ---- merged GAT gather: warp per dst node, half-warp per edge, row-prefetch depth 2 ----
__global__ void gat_gather3(GatJobs jobs) {
    int w = (blockIdx.x * blockDim.x + threadIdx.x) >> 5;
    int lane = threadIdx.x & 31;
    if (w >= jobs.ntot) return;
    GatJob jb;
    int node;
    if (w < jobs.n0)        { jb = jobs.j[0]; node = w; }
    else if (w < jobs.n01)  { jb = jobs.j[1]; node = w - jobs.n0; }
    else                    { jb = jobs.j[2]; node = w - jobs.n01; }

    int h = lane & 15;
    int half = lane >> 4;
    float4 fdv = ((const float4*)(jb.fd + (size_t)node * 64))[h];
    float4 at  = ((const float4*)jb.attn)[h];
    int b = jb.off[node], e = jb.off[node + 1];
    const float* fs = jb.fs;
    const int* val = jb.val;

    float denom = 0.f;
    float4 acc = make_float4(0.f, 0.f, 0.f, 0.f);
    int nit = (e - b + 1) >> 1;        // warp-uniform trip count
    int basej = b + half;              // this half's edges: basej, basej+2, ...

    float4 A0 = make_float4(0.f, 0.f, 0.f, 0.f);
    float4 A1 = A0;
    if (nit > 0)
        A0 = ((const float4*)(fs + (size_t)val[min(basej, e - 1)] * 64))[h];
    if (nit > 1)
        A1 = ((const float4*)(fs + (size_t)val[min(basej + 2, e - 1)] * 64))[h];

    for (int it = 0; it < nit; it++) {
        float4 A = A0;
        A0 = A1;
        if (it + 2 < nit)
            A1 = ((const float4*)(fs + (size_t)val[min(basej + 2 * (it + 2), e - 1)] * 64))[h];
        int j = basej + 2 * it;
        float x0 = A.x + fdv.x, x1 = A.y + fdv.y;
        float x2 = A.z + fdv.z, x3 = A.w + fdv.w;
        x0 = x0 > 0.f ? x0 : 0.2f * x0;
        x1 = x1 > 0.f ? x1 : 0.2f * x1;
        x2 = x2 > 0.f ? x2 : 0.2f * x2;
        x3 = x3 > 0.f ? x3 : 0.2f * x3;
        float p = x0 * at.x + x1 * at.y + x2 * at.z + x3 * at.w;
#pragma unroll
        for (int o = 8; o; o >>= 1) p += __shfl_xor_sync(0xffffffffu, p, o);
        float ex = (j < e) ? __expf(p) : 0.f;
        denom += ex;
        acc.x += ex * A.x;
        acc.y += ex * A.y;
        acc.z += ex * A.z;
        acc.w += ex * A.w;
    }
    // merge halves
    denom += __shfl_xor_sync(0xffffffffu, denom, 16);
    acc.x += __shfl_xor_sync(0xffffffffu, acc.x, 16);
    acc.y += __shfl_xor_sync(0xffffffffu, acc.y, 16);
    acc.z += __shfl_xor_sync(0xffffffffu, acc.z, 16);
    acc.w += __shfl_xor_sync(0xffffffffu, acc.w, 16);

    if (half == 0) {
        float inv = denom > 0.f ? 1.0f / denom : 0.f;
        float4 bv = ((const float4*)jb.bias)[h];
        float4 o4;
        o4.x = acc.x * inv + bv.x;
        o4.y = acc.y * inv + bv.y;
        o4.z = acc.z * inv + bv.z;
        o4.w = acc.w * inv + bv.w;
        if (jb.resid) {
            float4 rv = ((const float4*)(jb.resid + (size_t)node * jb.rstride))[h];
            o4.x += rv.x; o4.y += rv.y; o4.z += rv.z; o4.w += rv.w;
        }
        ((float4*)(jb.out + (size_t)node * jb.ostride))[h] = o4;
    }
}

// collapse gate MLP: v[k] = sum_j W1[k][j]*W2[j];  c = b1.W2 + b2
__global__ void gate_prep(const float* __restrict__ W1, const float* __restrict__ b1,
                          const float* __restrict__ W2, const float* __restrict__ b2,
                          float* __restrict__ gout) {
    int t = threadIdx.x;          // 256
    int i = t >> 7, k = t & 127;
    const float* w1 = W1 + (size_t)i * 128 * 128 + (size_t)k * 128;
    const float* w2 = W2 + i * 128;
    float v = 0.f;
    for (int j = 0; j < 128; j++) v += w1[j] * w2[j];
    gout[i * 132 + k] = v;
    if (k == 0) {
        float c = b2[i];
        const float* bb = b1 + i * 128;
        for (int j = 0; j < 128; j++) c += bb[j] * w2[j];
        gout[i * 132 + 128] = c;
    }
}

__global__ void z_kernel(const float* __restrict__ HU, const float* __restrict__ p,
                         const float* __restrict__ q, const float* __restrict__ gate,
                         float* __restrict__ zinf, float* __restrict__ zint,
                         float* __restrict__ sums, int n) {
    __shared__ float red[8][4];
    int w = (blockIdx.x * blockDim.x + threadIdx.x) >> 5;
    int wl = threadIdx.x >> 5;
    int lane = threadIdx.x & 31;
    float zi = 0.f, zt = 0.f;
    if (w < n) {
        float2 h  = ((const float2*)(HU + (size_t)w * HALL))[lane];
        float2 pv = ((const float2*)(p  + (size_t)w * 64))[lane];
        float2 qv = ((const float2*)(q  + (size_t)w * 64))[lane];
        const float2* vinf = (const float2*)gate;
        const float2* vint = (const float2*)(gate + 132);
        float2 vi0 = vinf[lane], vi1 = vinf[32 + lane];
        float2 vt0 = vint[lane], vt1 = vint[32 + lane];
        zi = h.x * vi0.x + h.y * vi0.y + pv.x * vi1.x + pv.y * vi1.y;
        zt = h.x * vt0.x + h.y * vt0.y + qv.x * vt1.x + qv.y * vt1.y;
    }
#pragma unroll
    for (int off = 16; off; off >>= 1) {
        zi += __shfl_down_sync(0xffffffffu, zi, off);
        zt += __shfl_down_sync(0xffffffffu, zt, off);
    }
    if (lane == 0) {
        if (w < n) {
            zi += gate[128]; zt += gate[132 + 128];
            zinf[w] = zi; zint[w] = zt;
            red[wl][0] = zi; red[wl][1] = zi * zi;
            red[wl][2] = zt; red[wl][3] = zt * zt;
        } else {
            red[wl][0] = red[wl][1] = red[wl][2] = red[wl][3] = 0.f;
        }
    }
    __syncthreads();
    if (threadIdx.x < 4) {
        float s = 0.f;
        for (int k = 0; k < 8; k++) s += red[k][threadIdx.x];
        atomicAdd(sums + threadIdx.x, s);
    }
}

__global__ void gate_apply(const float* __restrict__ HU, float* __restrict__ HUo,
                           const float* __restrict__ p, const float* __restrict__ q,
                           const float* __restrict__ zinf, const float* __restrict__ zint,
                           const float* __restrict__ sums, int n) {
    int w = (blockIdx.x * blockDim.x + threadIdx.x) >> 5;
    int lane = threadIdx.x & 31;
    if (w >= n) return;
    float inv = 1.0f / (float)n;
    float mu0 = sums[0] * inv;
    float var0 = sums[1] * inv - mu0 * mu0;
    float mu1 = sums[2] * inv;
    float var1 = sums[3] * inv - mu1 * mu1;
    float a0 = (zinf[w] - mu0) * rsqrtf(var0 + 1e-5f);
    float a1 = (zint[w] - mu1) * rsqrtf(var1 + 1e-5f);
    a0 = a0 > 0.f ? a0 : 0.01f * a0;
    a1 = a1 > 0.f ? a1 : 0.01f * a1;
    float m = fmaxf(a0, a1);
    float e0 = __expf(a0 - m), e1 = __expf(a1 - m);
    float g0 = e0 / (e0 + e1), g1 = e1 / (e0 + e1);
    float2 pv = ((const float2*)(p + (size_t)w * 64))[lane];
    float2 qv = ((const float2*)(q + (size_t)w * 64))[lane];
    float2 hv = ((const float2*)(HU + (size_t)w * HALL))[lane];
    float2 o;
    o.x = g0 * pv.x + g1 * qv.x + hv.x;
    o.y = g0 * pv.y + g1 * qv.y + hv.y;
    ((float2*)(HUo + (size_t)w * HALL))[lane] = o;
}

__global__ void pair_kernel(const int* __restrict__ uu, const int* __restrict__ ii,
                            const float* __restrict__ hu_all, const float* __restrict__ hi_all,
                            float* __restrict__ out, int np) {
    int w = (blockIdx.x * blockDim.x + threadIdx.x) >> 5;
    int lane = threadIdx.x & 31;
    if (w >= np) return;
    const float* hr = hu_all + (size_t)uu[w] * HALL;
    const float* ir = hi_all + (size_t)ii[w] * HALL;
    float s = 0.f;
#pragma unroll
    for (int c = 0; c < 6; c++) s += hr[lane + 32 * c] * ir[lane + 32 * c];
#pragma unroll
    for (int off = 16; off; off >>= 1) s += __shfl_down_sync(0xffffffffu, s, off);
    if (lane == 0) out[w] = s;
}

// ---------------- host ----------------

static float* sym_addr(const void* s) {
    void* p = nullptr;
    cudaGetSymbolAddress(&p, s);
    return (float*)p;
}

static void build_csr(const int* grp, const int* other, int E, int n,
                      int* off, int* val, int* deg, int* cursor, int* bsum) {
    int nb = (n + 4095) / 4096;
    cudaMemsetAsync(deg, 0, (size_t)n * sizeof(int));
    count_kernel<<<(E + 255) / 256, 256>>>(grp, deg, E);
    scan_bsums<<<nb, 256>>>(deg, n, bsum);
    scan_tops<<<1, 64>>>(bsum, nb, off + n);
    scan_final<<<nb, 256>>>(deg, n, bsum, off);
    cudaMemsetAsync(cursor, 0, (size_t)n * sizeof(int));
    scatter_kernel<<<(E + 255) / 256, 256>>>(grp, other, E, off, cursor, val);
}

extern "C" void kernel_launch(void* const* d_in, const int* in_sizes, int n_in,
                              void* d_out, int out_size) {
    int wf = -1, gf = -1;
    for (int i = 0; i < n_in; i++) {
        if (wf < 0 && in_sizes[i] == NUx * EMB) wf = i;   // eu
        if (gf < 0 && in_sizes[i] == ERx) gf = i;         // rate_src
    }
    if (wf < 0) wf = 0;
    if (gf < 0) gf = (wf == 0) ? 18 : 0;
    const float* eu        = (const float*)d_in[wf + 0];
    const float* ei        = (const float*)d_in[wf + 1];
    const float* rate_W    = (const float*)d_in[wf + 2];
    const float* rate_b    = (const float*)d_in[wf + 3];
    const float* rate_attn = (const float*)d_in[wf + 4];
    const float* rate_bias = (const float*)d_in[wf + 5];
    const float* rb_W      = (const float*)d_in[wf + 6];
    const float* rb_b      = (const float*)d_in[wf + 7];
    const float* rb_attn   = (const float*)d_in[wf + 8];
    const float* rb_bias   = (const float*)d_in[wf + 9];
    const float* tr_W      = (const float*)d_in[wf + 10];
    const float* tr_b      = (const float*)d_in[wf + 11];
    const float* tr_attn   = (const float*)d_in[wf + 12];
    const float* tr_bias   = (const float*)d_in[wf + 13];
    const float* attW1     = (const float*)d_in[wf + 14];
    const float* attb1     = (const float*)d_in[wf + 15];
    const float* attW2     = (const float*)d_in[wf + 16];
    const float* attb2     = (const float*)d_in[wf + 17];
    const int* rate_src  = (const int*)d_in[gf + 0];
    const int* rate_dst  = (const int*)d_in[gf + 1];
    const int* trust_src = (const int*)d_in[gf + 2];
    const int* trust_dst = (const int*)d_in[gf + 3];
    const int* pos_u     = (const int*)d_in[gf + 4];
    const int* pos_i     = (const int*)d_in[gf + 5];
    const int* neg_u     = (const int*)d_in[gf + 6];
    const int* neg_i     = (const int*)d_in[gf + 7];

    float* hu_all = sym_addr(g_hu_all);
    float* hi_all = sym_addr(g_hi_all);
    float* fsU_rate = sym_addr(g_fsU_rate);
    float* fdU_rb   = sym_addr(g_fdU_rb);
    float* fsU_tr   = sym_addr(g_fsU_tr);
    float* fdU_tr   = sym_addr(g_fdU_tr);
    float* fdI_rate = sym_addr(g_fdI_rate);
    float* fsI_rb   = sym_addr(g_fsI_rb);
    float* pbuf   = sym_addr(g_p);
    float* qbuf   = sym_addr(g_q);
    float* zinf   = sym_addr(g_zinf);
    float* zint   = sym_addr(g_zint);
    float* gate   = sym_addr(g_gate);
    float* sums   = sym_addr(g_sums);
    int* deg      = (int*)sym_addr(g_deg);
    int* cursor   = (int*)sym_addr(g_cursor);
    int* bsum     = (int*)sym_addr(g_bsum);
    int* off_item  = (int*)sym_addr(g_off_item);
    int* off_urate = (int*)sym_addr(g_off_urate);
    int* off_trust = (int*)sym_addr(g_off_trust);
    int* val_item  = (int*)sym_addr(g_val_item);
    int* val_urate = (int*)sym_addr(g_val_urate);
    int* val_trust = (int*)sym_addr(g_val_trust);
    float* out    = (float*)d_out;

    // Build CSRs (layer-invariant)
    build_csr(rate_dst,  rate_src,  ERx, NIx, off_item,  val_item,  deg, cursor, bsum);
    build_csr(rate_src,  rate_dst,  ERx, NUx, off_urate, val_urate, deg, cursor, bsum);
    build_csr(trust_dst, trust_src, ETx, NUx, off_trust, val_trust, deg, cursor, bsum);

    copy_block<<<(NUx * 64 + 255) / 256, 256>>>(eu, hu_all, HALL, NUx * 64);
    copy_block<<<(NIx * 64 + 255) / 256, 256>>>(ei, hi_all, HALL, NIx * 64);

    for (int l = 0; l < NLAYERS; l++) {
        const float* HU = hu_all + l * 64;        // stride HALL
        float* HUo      = hu_all + (l + 1) * 64;
        const float* HI = hi_all + l * 64;
        float* HIo      = hi_all + (l + 1) * 64;

        const float* rW = rate_W + (size_t)l * 2 * 4096;
        const float* rB = rate_b + (size_t)l * 2 * 64;
        const float* bW = rb_W   + (size_t)l * 2 * 4096;
        const float* bB = rb_b   + (size_t)l * 2 * 64;
        const float* tW = tr_W   + (size_t)l * 2 * 4096;
        const float* tB = tr_b   + (size_t)l * 2 * 64;

        GJobs ju;
        ju.m = 4;
        ju.j[0] = { rW,        rB,        fsU_rate };
        ju.j[1] = { bW + 4096, bB + 64,   fdU_rb   };
        ju.j[2] = { tW,        tB,        fsU_tr   };
        ju.j[3] = { tW + 4096, tB + 64,   fdU_tr   };
        gemm64_multi<<<(NUx + 63) / 64, 128>>>(HU, HALL, NUx, ju);

        GJobs ji;
        ji.m = 2;
        ji.j[0] = { rW + 4096, rB + 64,   fdI_rate };
        ji.j[1] = { bW,        bB,        fsI_rb   };
        ji.j[2] = { nullptr, nullptr, nullptr };
        ji.j[3] = { nullptr, nullptr, nullptr };
        gemm64_multi<<<(NIx + 63) / 64, 128>>>(HI, HALL, NIx, ji);

        GatJobs gj;
        gj.j[0] = { off_item,  val_item,  fsU_rate, fdI_rate,
                    rate_attn + l * 64, rate_bias + l * 64, HI, HALL, HIo, HALL, NIx };
        gj.j[1] = { off_urate, val_urate, fsI_rb,   fdU_rb,
                    rb_attn + l * 64,   rb_bias + l * 64, nullptr, 0, qbuf, 64, NUx };
        gj.j[2] = { off_trust, val_trust, fsU_tr,   fdU_tr,
                    tr_attn + l * 64,   tr_bias + l * 64, nullptr, 0, pbuf, 64, NUx };
        gj.n0 = NIx; gj.n01 = NIx + NUx; gj.ntot = NIx + 2 * NUx;
        gat_gather3<<<(gj.ntot * 32 + 255) / 256, 256>>>(gj);

        gate_prep<<<1, 256>>>(attW1 + (size_t)l * 2 * 128 * 128,
                              attb1 + (size_t)l * 2 * 128,
                              attW2 + (size_t)l * 2 * 128,
                              attb2 + (size_t)l * 2, gate);
        cudaMemsetAsync(sums, 0, 4 * sizeof(float));
        z_kernel<<<(NUx + 7) / 8, 256>>>(HU, pbuf, qbuf, gate, zinf, zint, sums, NUx);
        gate_apply<<<(NUx + 7) / 8, 256>>>(HU, HUo, pbuf, qbuf, zinf, zint, sums, NUx);
    }

    pair_kernel<<<(EPx + 7) / 8, 256>>>(pos_u, pos_i, hu_all, hi_all, out, EPx);
    pair_kernel<<<(EPx + 7) / 8, 256>>>(neg_u, neg_i, hu_all, hi_all, out + EPx, EPx);
}

// round 11
// speedup vs baseline: 1.1317x; 1.1317x over previous
#include <cuda_runtime.h>
#include <cuda_fp16.h>
#include <math.h>

#define EMB 64
#define NLAYERS 2
#define NUx 100000
#define NIx 50000
#define ERx 1000000
#define ETx 800000
#define EPx 200000
#define HALL 192   // EMB*(1+L)

// ---------------- static scratch (no allocations allowed) ----------------
__device__ float g_hu_all[(size_t)NUx * HALL];
__device__ float g_hi_all[(size_t)NIx * HALL];
// gather-source (fs) tables in fp16, gather-dest (fd) tables in fp32
__device__ __half g_fsU_rate[(size_t)NUx * EMB];
__device__ __half g_fsU_tr[(size_t)NUx * EMB];
__device__ __half g_fsI_rb[(size_t)NIx * EMB];
__device__ float g_fdU_rb[(size_t)NUx * EMB];
__device__ float g_fdU_tr[(size_t)NUx * EMB];
__device__ float g_fdI_rate[(size_t)NIx * EMB];
__device__ float g_p[(size_t)NUx * EMB];
__device__ float g_q[(size_t)NUx * EMB];
__device__ float g_zinf[NUx];
__device__ float g_zint[NUx];
__device__ float g_gate[264];
__device__ float g_sums[4];
__device__ int g_degU[NUx];
__device__ int g_degI[NIx];
__device__ int g_curU[NUx];
__device__ int g_curI[NIx];
__device__ int g_bsumU[64];
__device__ int g_bsumI[64];
__device__ int g_off_item[NIx + 1];
__device__ int g_off_urate[NUx + 1];
__device__ int g_off_trust[NUx + 1];
__device__ int g_val_item[ERx];
__device__ int g_val_urate[ERx];
__device__ int g_val_trust[ETx];

// ---------------- job descriptors ----------------
struct GJob { const float* W; const float* B; void* Y; int half; };
struct GJobs { GJob j[4]; int m; };

struct GatJob {
    const int* off; const int* val; const __half* fs; const float* fd;
    const float* attn; const float* bias; const float* resid; int rstride;
    float* out; int ostride; int n;
};
struct GatJobs { GatJob j[3]; int n0, n01, ntot; };

// ---------------- kernels ----------------

__global__ void copy_block(const float* __restrict__ src, float* __restrict__ dst,
                           int dstride, int n64) {
    int i = blockIdx.x * blockDim.x + threadIdx.x;
    if (i >= n64) return;
    int row = i >> 6, j = i & 63;
    dst[(size_t)row * dstride + j] = src[i];
}

// ---- CSR build ----
__global__ void count_kernel(const int* __restrict__ grp, int* __restrict__ deg, int E) {
    int e = blockIdx.x * blockDim.x + threadIdx.x;
    if (e < E) atomicAdd(deg + grp[e], 1);
}

// combined count for the rate graph: both directions in one pass
__global__ void count_rate(const int* __restrict__ src, const int* __restrict__ dst,
                           int* __restrict__ degU, int* __restrict__ degI, int E) {
    int e = blockIdx.x * blockDim.x + threadIdx.x;
    if (e >= E) return;
    atomicAdd(degU + src[e], 1);
    atomicAdd(degI + dst[e], 1);
}

__global__ void scan_bsums(const int* __restrict__ deg, int n, int* __restrict__ bsum) {
    __shared__ int sh[256];
    int t = threadIdx.x;
    int base = blockIdx.x * 4096;
    int s = 0;
#pragma unroll
    for (int i = 0; i < 16; i++) {
        int idx = base + i * 256 + t;
        if (idx < n) s += deg[idx];
    }
    sh[t] = s;
    __syncthreads();
    for (int st = 128; st; st >>= 1) {
        if (t < st) sh[t] += sh[t + st];
        __syncthreads();
    }
    if (t == 0) bsum[blockIdx.x] = sh[0];
}

__global__ void scan_tops(int* __restrict__ bsum, int nb, int* __restrict__ total) {
    __shared__ int sh[64];
    int t = threadIdx.x;   // 64 threads
    int v = (t < nb) ? bsum[t] : 0;
    sh[t] = v;
    __syncthreads();
    for (int st = 1; st < 64; st <<= 1) {
        int x = (t >= st) ? sh[t - st] : 0;
        __syncthreads();
        sh[t] += x;
        __syncthreads();
    }
    if (t < nb) bsum[t] = sh[t] - v;     // exclusive
    if (t == 63) *total = sh[63];
}

__global__ void scan_final(const int* __restrict__ deg, int n,
                           const int* __restrict__ bsum, int* __restrict__ off) {
    __shared__ int sh[256];
    int t = threadIdx.x;
    int base = blockIdx.x * 4096 + t * 16;
    int local[16];
    int s = 0;
#pragma unroll
    for (int i = 0; i < 16; i++) {
        int idx = base + i;
        int d = (idx < n) ? deg[idx] : 0;
        local[i] = d;
        s += d;
    }
    sh[t] = s;
    __syncthreads();
    int v = s;
    for (int st = 1; st < 256; st <<= 1) {
        int x = (t >= st) ? sh[t - st] : 0;
        __syncthreads();
        sh[t] += x;
        __syncthreads();
    }
    int run = bsum[blockIdx.x] + sh[t] - v;
#pragma unroll
    for (int i = 0; i < 16; i++) {
        int idx = base + i;
        if (idx < n) off[idx] = run;
        run += local[i];
    }
}

__global__ void scatter_kernel(const int* __restrict__ grp, const int* __restrict__ other,
                               int E, const int* __restrict__ off,
                               int* __restrict__ cursor, int* __restrict__ val) {
    int e = blockIdx.x * blockDim.x + threadIdx.x;
    if (e >= E) return;
    int d = grp[e];
    int pos = off[d] + atomicAdd(cursor + d, 1);
    val[pos] = other[e];
}

// combined scatter for the rate graph: both CSRs in one pass
__global__ void scatter_rate(const int* __restrict__ src, const int* __restrict__ dst, int E,
                             const int* __restrict__ offU, const int* __restrict__ offI,
                             int* __restrict__ curU, int* __restrict__ curI,
                             int* __restrict__ valU, int* __restrict__ valI) {
    int e = blockIdx.x * blockDim.x + threadIdx.x;
    if (e >= E) return;
    int s = src[e], d = dst[e];
    int pI = offI[d] + atomicAdd(curI + d, 1);
    valI[pI] = s;
    int pU = offU[s] + atomicAdd(curU + s, 1);
    valU[pU] = d;
}

// ---- batched GEMM (R5 version): 256 threads, 64-row tile, 4x4 per thread ----
__global__ void gemm64_multi(const float* __restrict__ X, int xstride, int n, GJobs jobs) {
    __shared__ float sW[2][4096];
    __shared__ float sXT[64 * 68];
    int tx = threadIdx.x;
    int row0 = blockIdx.x * 64;

    {
        int r = tx & 63, qu = tx >> 6;
        int row = row0 + r;
        if (row < n) {
            const float4* xr = (const float4*)(X + (size_t)row * xstride);
#pragma unroll
            for (int j = 0; j < 4; j++) {
                float4 v = xr[qu * 4 + j];
                int k = qu * 16 + j * 4;
                sXT[(k + 0) * 68 + r] = v.x;
                sXT[(k + 1) * 68 + r] = v.y;
                sXT[(k + 2) * 68 + r] = v.z;
                sXT[(k + 3) * 68 + r] = v.w;
            }
        } else {
#pragma unroll
            for (int j = 0; j < 4; j++) {
                int k = qu * 16 + j * 4;
                sXT[(k + 0) * 68 + r] = 0.f;
                sXT[(k + 1) * 68 + r] = 0.f;
                sXT[(k + 2) * 68 + r] = 0.f;
                sXT[(k + 3) * 68 + r] = 0.f;
            }
        }
    }
    for (int i = tx; i < 1024; i += 256)
        ((float4*)sW[0])[i] = ((const float4*)jobs.j[0].W)[i];
    __syncthreads();

    int ty = tx >> 4;    // rows 4ty..4ty+3
    int c  = tx & 15;    // cols 4c..4c+3
    int rbase = row0 + 4 * ty;

    for (int m = 0; m < jobs.m; m++) {
        const float* Bm; void* Ym; int halfm;
        const float* Wnext = nullptr;
        switch (m) {
            case 0: Bm = jobs.j[0].B; Ym = jobs.j[0].Y; halfm = jobs.j[0].half; break;
            case 1: Bm = jobs.j[1].B; Ym = jobs.j[1].Y; halfm = jobs.j[1].half; break;
            case 2: Bm = jobs.j[2].B; Ym = jobs.j[2].Y; halfm = jobs.j[2].half; break;
            default: Bm = jobs.j[3].B; Ym = jobs.j[3].Y; halfm = jobs.j[3].half; break;
        }
        if (m + 1 < jobs.m) {
            switch (m + 1) {
                case 1: Wnext = jobs.j[1].W; break;
                case 2: Wnext = jobs.j[2].W; break;
                default: Wnext = jobs.j[3].W; break;
            }
        }
        if (Wnext) {
            float4* wd = (float4*)sW[(m + 1) & 1];
            const float4* ws = (const float4*)Wnext;
            for (int i = tx; i < 1024; i += 256) wd[i] = ws[i];
        }
        const float* Wcur = sW[m & 1];

        float4 b0 = *(const float4*)(Bm + 4 * c);
        unsigned long long blo, bhi;
        asm("mov.b64 %0, {%1,%2};" : "=l"(blo) : "f"(b0.x), "f"(b0.y));
        asm("mov.b64 %0, {%1,%2};" : "=l"(bhi) : "f"(b0.z), "f"(b0.w));
        unsigned long long acc[4][2];
#pragma unroll
        for (int r = 0; r < 4; r++) { acc[r][0] = blo; acc[r][1] = bhi; }

#pragma unroll
        for (int k = 0; k < 64; k++) {
            ulonglong2 wv = ((const ulonglong2*)Wcur)[k * 16 + c];
            float4 a4 = *(const float4*)(sXT + k * 68 + 4 * ty);
            unsigned long long pa0, pa1, pa2, pa3;
            asm("mov.b64 %0, {%1,%1};" : "=l"(pa0) : "f"(a4.x));
            asm("mov.b64 %0, {%1,%1};" : "=l"(pa1) : "f"(a4.y));
            asm("mov.b64 %0, {%1,%1};" : "=l"(pa2) : "f"(a4.z));
            asm("mov.b64 %0, {%1,%1};" : "=l"(pa3) : "f"(a4.w));
            asm("fma.rn.f32x2 %0, %1, %2, %0;" : "+l"(acc[0][0]) : "l"(pa0), "l"(wv.x));
            asm("fma.rn.f32x2 %0, %1, %2, %0;" : "+l"(acc[0][1]) : "l"(pa0), "l"(wv.y));
            asm("fma.rn.f32x2 %0, %1, %2, %0;" : "+l"(acc[1][0]) : "l"(pa1), "l"(wv.x));
            asm("fma.rn.f32x2 %0, %1, %2, %0;" : "+l"(acc[1][1]) : "l"(pa1), "l"(wv.y));
            asm("fma.rn.f32x2 %0, %1, %2, %0;" : "+l"(acc[2][0]) : "l"(pa2), "l"(wv.x));
            asm("fma.rn.f32x2 %0, %1, %2, %0;" : "+l"(acc[2][1]) : "l"(pa2), "l"(wv.y));
            asm("fma.rn.f32x2 %0, %1, %2, %0;" : "+l"(acc[3][0]) : "l"(pa3), "l"(wv.x));
            asm("fma.rn.f32x2 %0, %1, %2, %0;" : "+l"(acc[3][1]) : "l"(pa3), "l"(wv.y));
        }
#pragma unroll
        for (int r = 0; r < 4; r++) {
            if (rbase + r < n) {
                float2 v01 = *(float2*)&acc[r][0];
                float2 v23 = *(float2*)&acc[r][1];
                if (halfm) {
                    __half2 h01 = __floats2half2_rn(v01.x, v01.y);
                    __half2 h23 = __floats2half2_rn(v23.x, v23.y);
                    uint2 st = make_uint2(*(unsigned int*)&h01, *(unsigned int*)&h23);
                    *(uint2*)((__half*)Ym + (size_t)(rbase + r) * 64 + 4 * c) = st;
                } else {
                    ulonglong2 o = make_ulonglong2(acc[r][0], acc[r][1]);
                    *(ulonglong2*)((float*)Ym + (size_t)(rbase + r) * 64 + 4 * c) = o;
                }
            }
        }
        __syncthreads();
    }
}

// ---- merged GAT gather: warp per dst node, half-warp per edge, fp16 fs rows ----
__global__ void gat_gather3(GatJobs jobs) {
    int w = (blockIdx.x * blockDim.x + threadIdx.x) >> 5;
    int lane = threadIdx.x & 31;
    if (w >= jobs.ntot) return;
    GatJob jb;
    int node;
    if (w < jobs.n0)        { jb = jobs.j[0]; node = w; }
    else if (w < jobs.n01)  { jb = jobs.j[1]; node = w - jobs.n0; }
    else                    { jb = jobs.j[2]; node = w - jobs.n01; }

    int h = lane & 15;
    int half = lane >> 4;
    float4 fdv = ((const float4*)(jb.fd + (size_t)node * 64))[h];
    float4 at  = ((const float4*)jb.attn)[h];
    int b = jb.off[node], e = jb.off[node + 1];
    const __half* fs = jb.fs;
    const int* val = jb.val;

    float denom = 0.f;
    float4 acc = make_float4(0.f, 0.f, 0.f, 0.f);
    int nit = (e - b + 1) >> 1;        // warp-uniform trip count
    int basej = b + half;              // this half's edges: basej, basej+2, ...

    uint2 A0r = make_uint2(0, 0);
    uint2 A1r = A0r;
    if (nit > 0)
        A0r = ((const uint2*)(fs + (size_t)val[min(basej, e - 1)] * 64))[h];
    if (nit > 1)
        A1r = ((const uint2*)(fs + (size_t)val[min(basej + 2, e - 1)] * 64))[h];

    for (int it = 0; it < nit; it++) {
        uint2 Ar = A0r;
        A0r = A1r;
        if (it + 2 < nit)
            A1r = ((const uint2*)(fs + (size_t)val[min(basej + 2 * (it + 2), e - 1)] * 64))[h];
        __half2* ah = (__half2*)&Ar;
        float2 a01 = __half22float2(ah[0]);
        float2 a23 = __half22float2(ah[1]);
        int j = basej + 2 * it;
        float x0 = a01.x + fdv.x, x1 = a01.y + fdv.y;
        float x2 = a23.x + fdv.z, x3 = a23.y + fdv.w;
        x0 = x0 > 0.f ? x0 : 0.2f * x0;
        x1 = x1 > 0.f ? x1 : 0.2f * x1;
        x2 = x2 > 0.f ? x2 : 0.2f * x2;
        x3 = x3 > 0.f ? x3 : 0.2f * x3;
        float p = x0 * at.x + x1 * at.y + x2 * at.z + x3 * at.w;
#pragma unroll
        for (int o = 8; o; o >>= 1) p += __shfl_xor_sync(0xffffffffu, p, o);
        float ex = (j < e) ? __expf(p) : 0.f;
        denom += ex;
        acc.x += ex * a01.x;
        acc.y += ex * a01.y;
        acc.z += ex * a23.x;
        acc.w += ex * a23.y;
    }
    // merge halves
    denom += __shfl_xor_sync(0xffffffffu, denom, 16);
    acc.x += __shfl_xor_sync(0xffffffffu, acc.x, 16);
    acc.y += __shfl_xor_sync(0xffffffffu, acc.y, 16);
    acc.z += __shfl_xor_sync(0xffffffffu, acc.z, 16);
    acc.w += __shfl_xor_sync(0xffffffffu, acc.w, 16);

    if (half == 0) {
        float inv = denom > 0.f ? 1.0f / denom : 0.f;
        float4 bv = ((const float4*)jb.bias)[h];
        float4 o4;
        o4.x = acc.x * inv + bv.x;
        o4.y = acc.y * inv + bv.y;
        o4.z = acc.z * inv + bv.z;
        o4.w = acc.w * inv + bv.w;
        if (jb.resid) {
            float4 rv = ((const float4*)(jb.resid + (size_t)node * jb.rstride))[h];
            o4.x += rv.x; o4.y += rv.y; o4.z += rv.z; o4.w += rv.w;
        }
        ((float4*)(jb.out + (size_t)node * jb.ostride))[h] = o4;
    }
}

// collapse gate MLP: v[k] = sum_j W1[k][j]*W2[j];  c = b1.W2 + b2
__global__ void gate_prep(const float* __restrict__ W1, const float* __restrict__ b1,
                          const float* __restrict__ W2, const float* __restrict__ b2,
                          float* __restrict__ gout) {
    int t = threadIdx.x;          // 256
    int i = t >> 7, k = t & 127;
    const float* w1 = W1 + (size_t)i * 128 * 128 + (size_t)k * 128;
    const float* w2 = W2 + i * 128;
    float v = 0.f;
    for (int j = 0; j < 128; j++) v += w1[j] * w2[j];
    gout[i * 132 + k] = v;
    if (k == 0) {
        float c = b2[i];
        const float* bb = b1 + i * 128;
        for (int j = 0; j < 128; j++) c += bb[j] * w2[j];
        gout[i * 132 + 128] = c;
    }
}

__global__ void z_kernel(const float* __restrict__ HU, const float* __restrict__ p,
                         const float* __restrict__ q, const float* __restrict__ gate,
                         float* __restrict__ zinf, float* __restrict__ zint,
                         float* __restrict__ sums, int n) {
    __shared__ float red[8][4];
    int w = (blockIdx.x * blockDim.x + threadIdx.x) >> 5;
    int wl = threadIdx.x >> 5;
    int lane = threadIdx.x & 31;
    float zi = 0.f, zt = 0.f;
    if (w < n) {
        float2 h  = ((const float2*)(HU + (size_t)w * HALL))[lane];
        float2 pv = ((const float2*)(p  + (size_t)w * 64))[lane];
        float2 qv = ((const float2*)(q  + (size_t)w * 64))[lane];
        const float2* vinf = (const float2*)gate;
        const float2* vint = (const float2*)(gate + 132);
        float2 vi0 = vinf[lane], vi1 = vinf[32 + lane];
        float2 vt0 = vint[lane], vt1 = vint[32 + lane];
        zi = h.x * vi0.x + h.y * vi0.y + pv.x * vi1.x + pv.y * vi1.y;
        zt = h.x * vt0.x + h.y * vt0.y + qv.x * vt1.x + qv.y * vt1.y;
    }
#pragma unroll
    for (int off = 16; off; off >>= 1) {
        zi += __shfl_down_sync(0xffffffffu, zi, off);
        zt += __shfl_down_sync(0xffffffffu, zt, off);
    }
    if (lane == 0) {
        if (w < n) {
            zi += gate[128]; zt += gate[132 + 128];
            zinf[w] = zi; zint[w] = zt;
            red[wl][0] = zi; red[wl][1] = zi * zi;
            red[wl][2] = zt; red[wl][3] = zt * zt;
        } else {
            red[wl][0] = red[wl][1] = red[wl][2] = red[wl][3] = 0.f;
        }
    }
    __syncthreads();
    if (threadIdx.x < 4) {
        float s = 0.f;
        for (int k = 0; k < 8; k++) s += red[k][threadIdx.x];
        atomicAdd(sums + threadIdx.x, s);
    }
}

__global__ void gate_apply(const float* __restrict__ HU, float* __restrict__ HUo,
                           const float* __restrict__ p, const float* __restrict__ q,
                           const float* __restrict__ zinf, const float* __restrict__ zint,
                           const float* __restrict__ sums, int n) {
    int w = (blockIdx.x * blockDim.x + threadIdx.x) >> 5;
    int lane = threadIdx.x & 31;
    if (w >= n) return;
    float inv = 1.0f / (float)n;
    float mu0 = sums[0] * inv;
    float var0 = sums[1] * inv - mu0 * mu0;
    float mu1 = sums[2] * inv;
    float var1 = sums[3] * inv - mu1 * mu1;
    float a0 = (zinf[w] - mu0) * rsqrtf(var0 + 1e-5f);
    float a1 = (zint[w] - mu1) * rsqrtf(var1 + 1e-5f);
    a0 = a0 > 0.f ? a0 : 0.01f * a0;
    a1 = a1 > 0.f ? a1 : 0.01f * a1;
    float m = fmaxf(a0, a1);
    float e0 = __expf(a0 - m), e1 = __expf(a1 - m);
    float g0 = e0 / (e0 + e1), g1 = e1 / (e0 + e1);
    float2 pv = ((const float2*)(p + (size_t)w * 64))[lane];
    float2 qv = ((const float2*)(q + (size_t)w * 64))[lane];
    float2 hv = ((const float2*)(HU + (size_t)w * HALL))[lane];
    float2 o;
    o.x = g0 * pv.x + g1 * qv.x + hv.x;
    o.y = g0 * pv.y + g1 * qv.y + hv.y;
    ((float2*)(HUo + (size_t)w * HALL))[lane] = o;
}

__global__ void pair_kernel(const int* __restrict__ uu, const int* __restrict__ ii,
                            const float* __restrict__ hu_all, const float* __restrict__ hi_all,
                            float* __restrict__ out, int np) {
    int w = (blockIdx.x * blockDim.x + threadIdx.x) >> 5;
    int lane = threadIdx.x & 31;
    if (w >= np) return;
    const float* hr = hu_all + (size_t)uu[w] * HALL;
    const float* ir = hi_all + (size_t)ii[w] * HALL;
    float s = 0.f;
#pragma unroll
    for (int c = 0; c < 6; c++) s += hr[lane + 32 * c] * ir[lane + 32 * c];
#pragma unroll
    for (int off = 16; off; off >>= 1) s += __shfl_down_sync(0xffffffffu, s, off);
    if (lane == 0) out[w] = s;
}

// ---------------- host ----------------

static void* sym_addr(const void* s) {
    void* p = nullptr;
    cudaGetSymbolAddress(&p, s);
    return p;
}

extern "C" void kernel_launch(void* const* d_in, const int* in_sizes, int n_in,
                              void* d_out, int out_size) {
    int wf = -1, gf = -1;
    for (int i = 0; i < n_in; i++) {
        if (wf < 0 && in_sizes[i] == NUx * EMB) wf = i;   // eu
        if (gf < 0 && in_sizes[i] == ERx) gf = i;         // rate_src
    }
    if (wf < 0) wf = 0;
    if (gf < 0) gf = (wf == 0) ? 18 : 0;
    const float* eu        = (const float*)d_in[wf + 0];
    const float* ei        = (const float*)d_in[wf + 1];
    const float* rate_W    = (const float*)d_in[wf + 2];
    const float* rate_b    = (const float*)d_in[wf + 3];
    const float* rate_attn = (const float*)d_in[wf + 4];
    const float* rate_bias = (const float*)d_in[wf + 5];
    const float* rb_W      = (const float*)d_in[wf + 6];
    const float* rb_b      = (const float*)d_in[wf + 7];
    const float* rb_attn   = (const float*)d_in[wf + 8];
    const float* rb_bias   = (const float*)d_in[wf + 9];
    const float* tr_W      = (const float*)d_in[wf + 10];
    const float* tr_b      = (const float*)d_in[wf + 11];
    const float* tr_attn   = (const float*)d_in[wf + 12];
    const float* tr_bias   = (const float*)d_in[wf + 13];
    const float* attW1     = (const float*)d_in[wf + 14];
    const float* attb1     = (const float*)d_in[wf + 15];
    const float* attW2     = (const float*)d_in[wf + 16];
    const float* attb2     = (const float*)d_in[wf + 17];
    const int* rate_src  = (const int*)d_in[gf + 0];
    const int* rate_dst  = (const int*)d_in[gf + 1];
    const int* trust_src = (const int*)d_in[gf + 2];
    const int* trust_dst = (const int*)d_in[gf + 3];
    const int* pos_u     = (const int*)d_in[gf + 4];
    const int* pos_i     = (const int*)d_in[gf + 5];
    const int* neg_u     = (const int*)d_in[gf + 6];
    const int* neg_i     = (const int*)d_in[gf + 7];

    float* hu_all = (float*)sym_addr(g_hu_all);
    float* hi_all = (float*)sym_addr(g_hi_all);
    __half* fsU_rate = (__half*)sym_addr(g_fsU_rate);
    __half* fsU_tr   = (__half*)sym_addr(g_fsU_tr);
    __half* fsI_rb   = (__half*)sym_addr(g_fsI_rb);
    float* fdU_rb   = (float*)sym_addr(g_fdU_rb);
    float* fdU_tr   = (float*)sym_addr(g_fdU_tr);
    float* fdI_rate = (float*)sym_addr(g_fdI_rate);
    float* pbuf   = (float*)sym_addr(g_p);
    float* qbuf   = (float*)sym_addr(g_q);
    float* zinf   = (float*)sym_addr(g_zinf);
    float* zint   = (float*)sym_addr(g_zint);
    float* gate   = (float*)sym_addr(g_gate);
    float* sums   = (float*)sym_addr(g_sums);
    int* degU     = (int*)sym_addr(g_degU);
    int* degI     = (int*)sym_addr(g_degI);
    int* curU     = (int*)sym_addr(g_curU);
    int* curI     = (int*)sym_addr(g_curI);
    int* bsumU    = (int*)sym_addr(g_bsumU);
    int* bsumI    = (int*)sym_addr(g_bsumI);
    int* off_item  = (int*)sym_addr(g_off_item);
    int* off_urate = (int*)sym_addr(g_off_urate);
    int* off_trust = (int*)sym_addr(g_off_trust);
    int* val_item  = (int*)sym_addr(g_val_item);
    int* val_urate = (int*)sym_addr(g_val_urate);
    int* val_trust = (int*)sym_addr(g_val_trust);
    float* out    = (float*)d_out;

    // ---- CSR build (layer-invariant) ----
    int nbU = (NUx + 4095) / 4096;   // 25
    int nbI = (NIx + 4095) / 4096;   // 13
    // rate graph: both directions in one count + one scatter
    cudaMemsetAsync(degU, 0, (size_t)NUx * sizeof(int));
    cudaMemsetAsync(degI, 0, (size_t)NIx * sizeof(int));
    count_rate<<<(ERx + 255) / 256, 256>>>(rate_src, rate_dst, degU, degI, ERx);
    scan_bsums<<<nbU, 256>>>(degU, NUx, bsumU);
    scan_tops<<<1, 64>>>(bsumU, nbU, off_urate + NUx);
    scan_final<<<nbU, 256>>>(degU, NUx, bsumU, off_urate);
    scan_bsums<<<nbI, 256>>>(degI, NIx, bsumI);
    scan_tops<<<1, 64>>>(bsumI, nbI, off_item + NIx);
    scan_final<<<nbI, 256>>>(degI, NIx, bsumI, off_item);
    cudaMemsetAsync(curU, 0, (size_t)NUx * sizeof(int));
    cudaMemsetAsync(curI, 0, (size_t)NIx * sizeof(int));
    scatter_rate<<<(ERx + 255) / 256, 256>>>(rate_src, rate_dst, ERx,
                                             off_urate, off_item, curU, curI,
                                             val_urate, val_item);
    // trust graph (reuses degU/curU)
    cudaMemsetAsync(degU, 0, (size_t)NUx * sizeof(int));
    count_kernel<<<(ETx + 255) / 256, 256>>>(trust_dst, degU, ETx);
    scan_bsums<<<nbU, 256>>>(degU, NUx, bsumU);
    scan_tops<<<1, 64>>>(bsumU, nbU, off_trust + NUx);
    scan_final<<<nbU, 256>>>(degU, NUx, bsumU, off_trust);
    cudaMemsetAsync(curU, 0, (size_t)NUx * sizeof(int));
    scatter_kernel<<<(ETx + 255) / 256, 256>>>(trust_dst, trust_src, ETx,
                                               off_trust, curU, val_trust);

    copy_block<<<(NUx * 64 + 255) / 256, 256>>>(eu, hu_all, HALL, NUx * 64);
    copy_block<<<(NIx * 64 + 255) / 256, 256>>>(ei, hi_all, HALL, NIx * 64);

    for (int l = 0; l < NLAYERS; l++) {
        const float* HU = hu_all + l * 64;        // stride HALL
        float* HUo      = hu_all + (l + 1) * 64;
        const float* HI = hi_all + l * 64;
        float* HIo      = hi_all + (l + 1) * 64;

        const float* rW = rate_W + (size_t)l * 2 * 4096;
        const float* rB = rate_b + (size_t)l * 2 * 64;
        const float* bW = rb_W   + (size_t)l * 2 * 4096;
        const float* bB = rb_b   + (size_t)l * 2 * 64;
        const float* tW = tr_W   + (size_t)l * 2 * 4096;
        const float* tB = tr_b   + (size_t)l * 2 * 64;

        GJobs ju;
        ju.m = 4;
        ju.j[0] = { rW,        rB,        (void*)fsU_rate, 1 };
        ju.j[1] = { bW + 4096, bB + 64,   (void*)fdU_rb,   0 };
        ju.j[2] = { tW,        tB,        (void*)fsU_tr,   1 };
        ju.j[3] = { tW + 4096, tB + 64,   (void*)fdU_tr,   0 };
        gemm64_multi<<<(NUx + 63) / 64, 256>>>(HU, HALL, NUx, ju);

        GJobs ji;
        ji.m = 2;
        ji.j[0] = { rW + 4096, rB + 64,   (void*)fdI_rate, 0 };
        ji.j[1] = { bW,        bB,        (void*)fsI_rb,   1 };
        ji.j[2] = { nullptr, nullptr, nullptr, 0 };
        ji.j[3] = { nullptr, nullptr, nullptr, 0 };
        gemm64_multi<<<(NIx + 63) / 64, 256>>>(HI, HALL, NIx, ji);

        GatJobs gj;
        gj.j[0] = { off_item,  val_item,  fsU_rate, fdI_rate,
                    rate_attn + l * 64, rate_bias + l * 64, HI, HALL, HIo, HALL, NIx };
        gj.j[1] = { off_urate, val_urate, fsI_rb,   fdU_rb,
                    rb_attn + l * 64,   rb_bias + l * 64, nullptr, 0, qbuf, 64, NUx };
        gj.j[2] = { off_trust, val_trust, fsU_tr,   fdU_tr,
                    tr_attn + l * 64,   tr_bias + l * 64, nullptr, 0, pbuf, 64, NUx };
        gj.n0 = NIx; gj.n01 = NIx + NUx; gj.ntot = NIx + 2 * NUx;
        gat_gather3<<<(gj.ntot * 32 + 255) / 256, 256>>>(gj);

        gate_prep<<<1, 256>>>(attW1 + (size_t)l * 2 * 128 * 128,
                              attb1 + (size_t)l * 2 * 128,
                              attW2 + (size_t)l * 2 * 128,
                              attb2 + (size_t)l * 2, gate);
        cudaMemsetAsync(sums, 0, 4 * sizeof(float));
        z_kernel<<<(NUx + 7) / 8, 256>>>(HU, pbuf, qbuf, gate, zinf, zint, sums, NUx);
        gate_apply<<<(NUx + 7) / 8, 256>>>(HU, HUo, pbuf, qbuf, zinf, zint, sums, NUx);
    }

    pair_kernel<<<(EPx + 7) / 8, 256>>>(pos_u, pos_i, hu_all, hi_all, out, EPx);
    pair_kernel<<<(EPx + 7) / 8, 256>>>(neg_u, neg_i, hu_all, hi_all, out + EPx, EPx);
}

// round 12
// speedup vs baseline: 1.3178x; 1.1644x over previous
#include <cuda_runtime.h>
#include <cuda_fp16.h>
#include <math.h>

#define EMB 64
#define NLAYERS 2
#define NUx 100000
#define NIx 50000
#define ERx 1000000
#define ETx 800000
#define EPx 200000
#define HALL 192   // EMB*(1+L)

// ---------------- static scratch (no allocations allowed) ----------------
__device__ float g_hu_all[(size_t)NUx * HALL];
__device__ float g_hi_all[(size_t)NIx * HALL];
// gather-source (fs) tables in fp16, gather-dest (fd) tables in fp32
__device__ __half g_fsU_rate[(size_t)NUx * EMB];
__device__ __half g_fsU_tr[(size_t)NUx * EMB];
__device__ __half g_fsI_rb[(size_t)NIx * EMB];
__device__ float g_fdU_rb[(size_t)NUx * EMB];
__device__ float g_fdU_tr[(size_t)NUx * EMB];
__device__ float g_fdI_rate[(size_t)NIx * EMB];
__device__ float g_p[(size_t)NUx * EMB];
__device__ float g_q[(size_t)NUx * EMB];
__device__ float g_zinf[NUx];
__device__ float g_zint[NUx];
__device__ float g_gate[264];
__device__ float g_sums[4];
__device__ int g_degU[NUx];
__device__ int g_degI[NIx];
__device__ int g_curU[NUx];
__device__ int g_curI[NIx];
__device__ int g_bsumU[64];
__device__ int g_bsumI[64];
__device__ int g_off_item[NIx + 1];
__device__ int g_off_urate[NUx + 1];
__device__ int g_off_trust[NUx + 1];
__device__ int g_val_item[ERx];
__device__ int g_val_urate[ERx];
__device__ int g_val_trust[ETx];

// ---------------- job descriptors ----------------
struct GJob { const float* W; const float* B; void* Y; int half; };
struct GJobs { GJob j[4]; int m; };

struct GatJob {
    const int* off; const int* val; const __half* fs; const float* fd;
    const float* attn; const float* bias; const float* resid; int rstride;
    float* out; int ostride; int n;
};
struct GatJobs { GatJob j[3]; int n0, n01, ntot; };

static __device__ __forceinline__ unsigned smem_u32(const void* p) {
    return (unsigned)__cvta_generic_to_shared(p);
}

// ---------------- kernels ----------------

__global__ void copy_block(const float* __restrict__ src, float* __restrict__ dst,
                           int dstride, int n64) {
    int i = blockIdx.x * blockDim.x + threadIdx.x;
    if (i >= n64) return;
    int row = i >> 6, j = i & 63;
    dst[(size_t)row * dstride + j] = src[i];
}

// ---- CSR build ----
__global__ void count_kernel(const int* __restrict__ grp, int* __restrict__ deg, int E) {
    int e = blockIdx.x * blockDim.x + threadIdx.x;
    if (e < E) atomicAdd(deg + grp[e], 1);
}

__global__ void count_rate(const int* __restrict__ src, const int* __restrict__ dst,
                           int* __restrict__ degU, int* __restrict__ degI, int E) {
    int e = blockIdx.x * blockDim.x + threadIdx.x;
    if (e >= E) return;
    atomicAdd(degU + src[e], 1);
    atomicAdd(degI + dst[e], 1);
}

__global__ void scan_bsums(const int* __restrict__ deg, int n, int* __restrict__ bsum) {
    __shared__ int sh[256];
    int t = threadIdx.x;
    int base = blockIdx.x * 4096;
    int s = 0;
#pragma unroll
    for (int i = 0; i < 16; i++) {
        int idx = base + i * 256 + t;
        if (idx < n) s += deg[idx];
    }
    sh[t] = s;
    __syncthreads();
    for (int st = 128; st; st >>= 1) {
        if (t < st) sh[t] += sh[t + st];
        __syncthreads();
    }
    if (t == 0) bsum[blockIdx.x] = sh[0];
}

__global__ void scan_tops(int* __restrict__ bsum, int nb, int* __restrict__ total) {
    __shared__ int sh[64];
    int t = threadIdx.x;   // 64 threads
    int v = (t < nb) ? bsum[t] : 0;
    sh[t] = v;
    __syncthreads();
    for (int st = 1; st < 64; st <<= 1) {
        int x = (t >= st) ? sh[t - st] : 0;
        __syncthreads();
        sh[t] += x;
        __syncthreads();
    }
    if (t < nb) bsum[t] = sh[t] - v;     // exclusive
    if (t == 63) *total = sh[63];
}

__global__ void scan_final(const int* __restrict__ deg, int n,
                           const int* __restrict__ bsum, int* __restrict__ off) {
    __shared__ int sh[256];
    int t = threadIdx.x;
    int base = blockIdx.x * 4096 + t * 16;
    int local[16];
    int s = 0;
#pragma unroll
    for (int i = 0; i < 16; i++) {
        int idx = base + i;
        int d = (idx < n) ? deg[idx] : 0;
        local[i] = d;
        s += d;
    }
    sh[t] = s;
    __syncthreads();
    int v = s;
    for (int st = 1; st < 256; st <<= 1) {
        int x = (t >= st) ? sh[t - st] : 0;
        __syncthreads();
        sh[t] += x;
        __syncthreads();
    }
    int run = bsum[blockIdx.x] + sh[t] - v;
#pragma unroll
    for (int i = 0; i < 16; i++) {
        int idx = base + i;
        if (idx < n) off[idx] = run;
        run += local[i];
    }
}

__global__ void scatter_kernel(const int* __restrict__ grp, const int* __restrict__ other,
                               int E, const int* __restrict__ off,
                               int* __restrict__ cursor, int* __restrict__ val) {
    int e = blockIdx.x * blockDim.x + threadIdx.x;
    if (e >= E) return;
    int d = grp[e];
    int pos = off[d] + atomicAdd(cursor + d, 1);
    val[pos] = other[e];
}

__global__ void scatter_rate(const int* __restrict__ src, const int* __restrict__ dst, int E,
                             const int* __restrict__ offU, const int* __restrict__ offI,
                             int* __restrict__ curU, int* __restrict__ curI,
                             int* __restrict__ valU, int* __restrict__ valI) {
    int e = blockIdx.x * blockDim.x + threadIdx.x;
    if (e >= E) return;
    int s = src[e], d = dst[e];
    int pI = offI[d] + atomicAdd(curI + d, 1);
    valI[pI] = s;
    int pU = offU[s] + atomicAdd(curU + s, 1);
    valU[pU] = d;
}

// ---- batched GEMM via fp16 tensor cores (mma.sync m16n8k16, fp32 accum) ----
// 128 threads = 4 warps; 64-row tile; warp handles 16 rows x 64 cols.
__global__ void gemm64_tc(const float* __restrict__ X, int xstride, int n, GJobs jobs) {
    __shared__ __half sX[64 * 72];
    __shared__ __half sWh[64 * 72];
    __shared__ float sB[64];
    int tx = threadIdx.x;            // 128
    int warp = tx >> 5, lane = tx & 31;
    int row0 = blockIdx.x * 64;

    // convert X tile to fp16 in smem: thread -> row r, 32 cols
    {
        int r = tx & 63, qu = tx >> 6;
        int row = row0 + r;
        if (row < n) {
            const float4* xr = (const float4*)(X + (size_t)row * xstride) + qu * 8;
#pragma unroll
            for (int j = 0; j < 8; j++) {
                float4 v = xr[j];
                __half2 h0 = __floats2half2_rn(v.x, v.y);
                __half2 h1 = __floats2half2_rn(v.z, v.w);
                *(uint2*)&sX[r * 72 + qu * 32 + j * 4] =
                    make_uint2(*(unsigned*)&h0, *(unsigned*)&h1);
            }
        } else {
#pragma unroll
            for (int j = 0; j < 8; j++)
                *(uint2*)&sX[r * 72 + qu * 32 + j * 4] = make_uint2(0u, 0u);
        }
    }

    int m0 = warp * 16;
    int g = lane >> 2;          // row within 8-row group
    int c2 = (lane & 3) * 2;    // col pair within 8-col tile

    for (int m = 0; m < jobs.m; m++) {
        const float* Wm; const float* Bm; void* Ym; int halfm;
        switch (m) {
            case 0: Wm = jobs.j[0].W; Bm = jobs.j[0].B; Ym = jobs.j[0].Y; halfm = jobs.j[0].half; break;
            case 1: Wm = jobs.j[1].W; Bm = jobs.j[1].B; Ym = jobs.j[1].Y; halfm = jobs.j[1].half; break;
            case 2: Wm = jobs.j[2].W; Bm = jobs.j[2].B; Ym = jobs.j[2].Y; halfm = jobs.j[2].half; break;
            default: Wm = jobs.j[3].W; Bm = jobs.j[3].B; Ym = jobs.j[3].Y; halfm = jobs.j[3].half; break;
        }
        __syncthreads();   // previous job's reads of sWh done; sX writes visible (m==0)
        // convert W to fp16 in smem
        for (int i = tx; i < 1024; i += 128) {
            float4 w = ((const float4*)Wm)[i];
            __half2 h0 = __floats2half2_rn(w.x, w.y);
            __half2 h1 = __floats2half2_rn(w.z, w.w);
            int r = i >> 4, c4 = (i & 15) * 4;
            *(uint2*)&sWh[r * 72 + c4] = make_uint2(*(unsigned*)&h0, *(unsigned*)&h1);
        }
        if (tx < 64) sB[tx] = Bm[tx];
        __syncthreads();

        float acc[8][4];
#pragma unroll
        for (int nt = 0; nt < 8; nt++)
#pragma unroll
            for (int q = 0; q < 4; q++) acc[nt][q] = 0.f;

#pragma unroll
        for (int kc = 0; kc < 4; kc++) {
            unsigned a0, a1, a2, a3;
            {
                int l8 = lane & 7;
                int rsel = (lane & 8) ? 8 : 0;
                int csel = (lane & 16) ? 8 : 0;
                unsigned aaddr = smem_u32(&sX[(m0 + l8 + rsel) * 72 + kc * 16 + csel]);
                asm volatile("ldmatrix.sync.aligned.m8n8.x4.shared.b16 {%0,%1,%2,%3}, [%4];"
                             : "=r"(a0), "=r"(a1), "=r"(a2), "=r"(a3) : "r"(aaddr));
            }
#pragma unroll
            for (int nt = 0; nt < 8; nt++) {
                unsigned b0, b1;
                int krow = kc * 16 + (lane & 15);
                unsigned baddr = smem_u32(&sWh[krow * 72 + nt * 8]);
                asm volatile("ldmatrix.sync.aligned.m8n8.x2.trans.shared.b16 {%0,%1}, [%2];"
                             : "=r"(b0), "=r"(b1) : "r"(baddr));
                asm volatile("mma.sync.aligned.m16n8k16.row.col.f32.f16.f16.f32 "
                             "{%0,%1,%2,%3}, {%4,%5,%6,%7}, {%8,%9}, {%0,%1,%2,%3};"
                             : "+f"(acc[nt][0]), "+f"(acc[nt][1]),
                               "+f"(acc[nt][2]), "+f"(acc[nt][3])
                             : "r"(a0), "r"(a1), "r"(a2), "r"(a3), "r"(b0), "r"(b1));
            }
        }

        // epilogue: add bias, store rows m0+g and m0+8+g
        int r1 = row0 + m0 + g;
        int r2 = r1 + 8;
#pragma unroll
        for (int nt = 0; nt < 8; nt++) {
            float bv0 = sB[nt * 8 + c2];
            float bv1 = sB[nt * 8 + c2 + 1];
            float v00 = acc[nt][0] + bv0, v01 = acc[nt][1] + bv1;
            float v10 = acc[nt][2] + bv0, v11 = acc[nt][3] + bv1;
            if (halfm) {
                __half* yh = (__half*)Ym;
                if (r1 < n) {
                    __half2 h = __floats2half2_rn(v00, v01);
                    *(__half2*)(yh + (size_t)r1 * 64 + nt * 8 + c2) = h;
                }
                if (r2 < n) {
                    __half2 h = __floats2half2_rn(v10, v11);
                    *(__half2*)(yh + (size_t)r2 * 64 + nt * 8 + c2) = h;
                }
            } else {
                float* yf = (float*)Ym;
                if (r1 < n) *(float2*)(yf + (size_t)r1 * 64 + nt * 8 + c2) = make_float2(v00, v01);
                if (r2 < n) *(float2*)(yf + (size_t)r2 * 64 + nt * 8 + c2) = make_float2(v10, v11);
            }
        }
    }
}

// ---- merged GAT gather: warp per dst node, half-warp per edge, fp16 fs rows ----
__global__ void gat_gather3(GatJobs jobs) {
    int w = (blockIdx.x * blockDim.x + threadIdx.x) >> 5;
    int lane = threadIdx.x & 31;
    if (w >= jobs.ntot) return;
    GatJob jb;
    int node;
    if (w < jobs.n0)        { jb = jobs.j[0]; node = w; }
    else if (w < jobs.n01)  { jb = jobs.j[1]; node = w - jobs.n0; }
    else                    { jb = jobs.j[2]; node = w - jobs.n01; }

    int h = lane & 15;
    int half = lane >> 4;
    float4 fdv = ((const float4*)(jb.fd + (size_t)node * 64))[h];
    float4 at  = ((const float4*)jb.attn)[h];
    int b = jb.off[node], e = jb.off[node + 1];
    const __half* fs = jb.fs;
    const int* val = jb.val;

    float denom = 0.f;
    float4 acc = make_float4(0.f, 0.f, 0.f, 0.f);
    int nit = (e - b + 1) >> 1;        // warp-uniform trip count
    int basej = b + half;              // this half's edges: basej, basej+2, ...

    uint2 A0r = make_uint2(0, 0);
    uint2 A1r = A0r;
    if (nit > 0)
        A0r = ((const uint2*)(fs + (size_t)val[min(basej, e - 1)] * 64))[h];
    if (nit > 1)
        A1r = ((const uint2*)(fs + (size_t)val[min(basej + 2, e - 1)] * 64))[h];

    for (int it = 0; it < nit; it++) {
        uint2 Ar = A0r;
        A0r = A1r;
        if (it + 2 < nit)
            A1r = ((const uint2*)(fs + (size_t)val[min(basej + 2 * (it + 2), e - 1)] * 64))[h];
        __half2* ah = (__half2*)&Ar;
        float2 a01 = __half22float2(ah[0]);
        float2 a23 = __half22float2(ah[1]);
        int j = basej + 2 * it;
        float x0 = a01.x + fdv.x, x1 = a01.y + fdv.y;
        float x2 = a23.x + fdv.z, x3 = a23.y + fdv.w;
        x0 = x0 > 0.f ? x0 : 0.2f * x0;
        x1 = x1 > 0.f ? x1 : 0.2f * x1;
        x2 = x2 > 0.f ? x2 : 0.2f * x2;
        x3 = x3 > 0.f ? x3 : 0.2f * x3;
        float p = x0 * at.x + x1 * at.y + x2 * at.z + x3 * at.w;
#pragma unroll
        for (int o = 8; o; o >>= 1) p += __shfl_xor_sync(0xffffffffu, p, o);
        float ex = (j < e) ? __expf(p) : 0.f;
        denom += ex;
        acc.x += ex * a01.x;
        acc.y += ex * a01.y;
        acc.z += ex * a23.x;
        acc.w += ex * a23.y;
    }
    // merge halves
    denom += __shfl_xor_sync(0xffffffffu, denom, 16);
    acc.x += __shfl_xor_sync(0xffffffffu, acc.x, 16);
    acc.y += __shfl_xor_sync(0xffffffffu, acc.y, 16);
    acc.z += __shfl_xor_sync(0xffffffffu, acc.z, 16);
    acc.w += __shfl_xor_sync(0xffffffffu, acc.w, 16);

    if (half == 0) {
        float inv = denom > 0.f ? 1.0f / denom : 0.f;
        float4 bv = ((const float4*)jb.bias)[h];
        float4 o4;
        o4.x = acc.x * inv + bv.x;
        o4.y = acc.y * inv + bv.y;
        o4.z = acc.z * inv + bv.z;
        o4.w = acc.w * inv + bv.w;
        if (jb.resid) {
            float4 rv = ((const float4*)(jb.resid + (size_t)node * jb.rstride))[h];
            o4.x += rv.x; o4.y += rv.y; o4.z += rv.z; o4.w += rv.w;
        }
        ((float4*)(jb.out + (size_t)node * jb.ostride))[h] = o4;
    }
}

// collapse gate MLP: v[k] = sum_j W1[k][j]*W2[j];  c = b1.W2 + b2
__global__ void gate_prep(const float* __restrict__ W1, const float* __restrict__ b1,
                          const float* __restrict__ W2, const float* __restrict__ b2,
                          float* __restrict__ gout) {
    int t = threadIdx.x;          // 256
    int i = t >> 7, k = t & 127;
    const float* w1 = W1 + (size_t)i * 128 * 128 + (size_t)k * 128;
    const float* w2 = W2 + i * 128;
    float v = 0.f;
    for (int j = 0; j < 128; j++) v += w1[j] * w2[j];
    gout[i * 132 + k] = v;
    if (k == 0) {
        float c = b2[i];
        const float* bb = b1 + i * 128;
        for (int j = 0; j < 128; j++) c += bb[j] * w2[j];
        gout[i * 132 + 128] = c;
    }
}

__global__ void z_kernel(const float* __restrict__ HU, const float* __restrict__ p,
                         const float* __restrict__ q, const float* __restrict__ gate,
                         float* __restrict__ zinf, float* __restrict__ zint,
                         float* __restrict__ sums, int n) {
    __shared__ float red[8][4];
    int w = (blockIdx.x * blockDim.x + threadIdx.x) >> 5;
    int wl = threadIdx.x >> 5;
    int lane = threadIdx.x & 31;
    float zi = 0.f, zt = 0.f;
    if (w < n) {
        float2 h  = ((const float2*)(HU + (size_t)w * HALL))[lane];
        float2 pv = ((const float2*)(p  + (size_t)w * 64))[lane];
        float2 qv = ((const float2*)(q  + (size_t)w * 64))[lane];
        const float2* vinf = (const float2*)gate;
        const float2* vint = (const float2*)(gate + 132);
        float2 vi0 = vinf[lane], vi1 = vinf[32 + lane];
        float2 vt0 = vint[lane], vt1 = vint[32 + lane];
        zi = h.x * vi0.x + h.y * vi0.y + pv.x * vi1.x + pv.y * vi1.y;
        zt = h.x * vt0.x + h.y * vt0.y + qv.x * vt1.x + qv.y * vt1.y;
    }
#pragma unroll
    for (int off = 16; off; off >>= 1) {
        zi += __shfl_down_sync(0xffffffffu, zi, off);
        zt += __shfl_down_sync(0xffffffffu, zt, off);
    }
    if (lane == 0) {
        if (w < n) {
            zi += gate[128]; zt += gate[132 + 128];
            zinf[w] = zi; zint[w] = zt;
            red[wl][0] = zi; red[wl][1] = zi * zi;
            red[wl][2] = zt; red[wl][3] = zt * zt;
        } else {
            red[wl][0] = red[wl][1] = red[wl][2] = red[wl][3] = 0.f;
        }
    }
    __syncthreads();
    if (threadIdx.x < 4) {
        float s = 0.f;
        for (int k = 0; k < 8; k++) s += red[k][threadIdx.x];
        atomicAdd(sums + threadIdx.x, s);
    }
}

__global__ void gate_apply(const float* __restrict__ HU, float* __restrict__ HUo,
                           const float* __restrict__ p, const float* __restrict__ q,
                           const float* __restrict__ zinf, const float* __restrict__ zint,
                           const float* __restrict__ sums, int n) {
    int w = (blockIdx.x * blockDim.x + threadIdx.x) >> 5;
    int lane = threadIdx.x & 31;
    if (w >= n) return;
    float inv = 1.0f / (float)n;
    float mu0 = sums[0] * inv;
    float var0 = sums[1] * inv - mu0 * mu0;
    float mu1 = sums[2] * inv;
    float var1 = sums[3] * inv - mu1 * mu1;
    float a0 = (zinf[w] - mu0) * rsqrtf(var0 + 1e-5f);
    float a1 = (zint[w] - mu1) * rsqrtf(var1 + 1e-5f);
    a0 = a0 > 0.f ? a0 : 0.01f * a0;
    a1 = a1 > 0.f ? a1 : 0.01f * a1;
    float m = fmaxf(a0, a1);
    float e0 = __expf(a0 - m), e1 = __expf(a1 - m);
    float g0 = e0 / (e0 + e1), g1 = e1 / (e0 + e1);
    float2 pv = ((const float2*)(p + (size_t)w * 64))[lane];
    float2 qv = ((const float2*)(q + (size_t)w * 64))[lane];
    float2 hv = ((const float2*)(HU + (size_t)w * HALL))[lane];
    float2 o;
    o.x = g0 * pv.x + g1 * qv.x + hv.x;
    o.y = g0 * pv.y + g1 * qv.y + hv.y;
    ((float2*)(HUo + (size_t)w * HALL))[lane] = o;
}

__global__ void pair_kernel(const int* __restrict__ uu, const int* __restrict__ ii,
                            const float* __restrict__ hu_all, const float* __restrict__ hi_all,
                            float* __restrict__ out, int np) {
    int w = (blockIdx.x * blockDim.x + threadIdx.x) >> 5;
    int lane = threadIdx.x & 31;
    if (w >= np) return;
    const float* hr = hu_all + (size_t)uu[w] * HALL;
    const float* ir = hi_all + (size_t)ii[w] * HALL;
    float s = 0.f;
#pragma unroll
    for (int c = 0; c < 6; c++) s += hr[lane + 32 * c] * ir[lane + 32 * c];
#pragma unroll
    for (int off = 16; off; off >>= 1) s += __shfl_down_sync(0xffffffffu, s, off);
    if (lane == 0) out[w] = s;
}

// ---------------- host ----------------

static void* sym_addr(const void* s) {
    void* p = nullptr;
    cudaGetSymbolAddress(&p, s);
    return p;
}

extern "C" void kernel_launch(void* const* d_in, const int* in_sizes, int n_in,
                              void* d_out, int out_size) {
    int wf = -1, gf = -1;
    for (int i = 0; i < n_in; i++) {
        if (wf < 0 && in_sizes[i] == NUx * EMB) wf = i;   // eu
        if (gf < 0 && in_sizes[i] == ERx) gf = i;         // rate_src
    }
    if (wf < 0) wf = 0;
    if (gf < 0) gf = (wf == 0) ? 18 : 0;
    const float* eu        = (const float*)d_in[wf + 0];
    const float* ei        = (const float*)d_in[wf + 1];
    const float* rate_W    = (const float*)d_in[wf + 2];
    const float* rate_b    = (const float*)d_in[wf + 3];
    const float* rate_attn = (const float*)d_in[wf + 4];
    const float* rate_bias = (const float*)d_in[wf + 5];
    const float* rb_W      = (const float*)d_in[wf + 6];
    const float* rb_b      = (const float*)d_in[wf + 7];
    const float* rb_attn   = (const float*)d_in[wf + 8];
    const float* rb_bias   = (const float*)d_in[wf + 9];
    const float* tr_W      = (const float*)d_in[wf + 10];
    const float* tr_b      = (const float*)d_in[wf + 11];
    const float* tr_attn   = (const float*)d_in[wf + 12];
    const float* tr_bias   = (const float*)d_in[wf + 13];
    const float* attW1     = (const float*)d_in[wf + 14];
    const float* attb1     = (const float*)d_in[wf + 15];
    const float* attW2     = (const float*)d_in[wf + 16];
    const float* attb2     = (const float*)d_in[wf + 17];
    const int* rate_src  = (const int*)d_in[gf + 0];
    const int* rate_dst  = (const int*)d_in[gf + 1];
    const int* trust_src = (const int*)d_in[gf + 2];
    const int* trust_dst = (const int*)d_in[gf + 3];
    const int* pos_u     = (const int*)d_in[gf + 4];
    const int* pos_i     = (const int*)d_in[gf + 5];
    const int* neg_u     = (const int*)d_in[gf + 6];
    const int* neg_i     = (const int*)d_in[gf + 7];

    float* hu_all = (float*)sym_addr(g_hu_all);
    float* hi_all = (float*)sym_addr(g_hi_all);
    __half* fsU_rate = (__half*)sym_addr(g_fsU_rate);
    __half* fsU_tr   = (__half*)sym_addr(g_fsU_tr);
    __half* fsI_rb   = (__half*)sym_addr(g_fsI_rb);
    float* fdU_rb   = (float*)sym_addr(g_fdU_rb);
    float* fdU_tr   = (float*)sym_addr(g_fdU_tr);
    float* fdI_rate = (float*)sym_addr(g_fdI_rate);
    float* pbuf   = (float*)sym_addr(g_p);
    float* qbuf   = (float*)sym_addr(g_q);
    float* zinf   = (float*)sym_addr(g_zinf);
    float* zint   = (float*)sym_addr(g_zint);
    float* gate   = (float*)sym_addr(g_gate);
    float* sums   = (float*)sym_addr(g_sums);
    int* degU     = (int*)sym_addr(g_degU);
    int* degI     = (int*)sym_addr(g_degI);
    int* curU     = (int*)sym_addr(g_curU);
    int* curI     = (int*)sym_addr(g_curI);
    int* bsumU    = (int*)sym_addr(g_bsumU);
    int* bsumI    = (int*)sym_addr(g_bsumI);
    int* off_item  = (int*)sym_addr(g_off_item);
    int* off_urate = (int*)sym_addr(g_off_urate);
    int* off_trust = (int*)sym_addr(g_off_trust);
    int* val_item  = (int*)sym_addr(g_val_item);
    int* val_urate = (int*)sym_addr(g_val_urate);
    int* val_trust = (int*)sym_addr(g_val_trust);
    float* out    = (float*)d_out;

    // ---- CSR build (layer-invariant) ----
    int nbU = (NUx + 4095) / 4096;   // 25
    int nbI = (NIx + 4095) / 4096;   // 13
    cudaMemsetAsync(degU, 0, (size_t)NUx * sizeof(int));
    cudaMemsetAsync(degI, 0, (size_t)NIx * sizeof(int));
    count_rate<<<(ERx + 255) / 256, 256>>>(rate_src, rate_dst, degU, degI, ERx);
    scan_bsums<<<nbU, 256>>>(degU, NUx, bsumU);
    scan_tops<<<1, 64>>>(bsumU, nbU, off_urate + NUx);
    scan_final<<<nbU, 256>>>(degU, NUx, bsumU, off_urate);
    scan_bsums<<<nbI, 256>>>(degI, NIx, bsumI);
    scan_tops<<<1, 64>>>(bsumI, nbI, off_item + NIx);
    scan_final<<<nbI, 256>>>(degI, NIx, bsumI, off_item);
    cudaMemsetAsync(curU, 0, (size_t)NUx * sizeof(int));
    cudaMemsetAsync(curI, 0, (size_t)NIx * sizeof(int));
    scatter_rate<<<(ERx + 255) / 256, 256>>>(rate_src, rate_dst, ERx,
                                             off_urate, off_item, curU, curI,
                                             val_urate, val_item);
    cudaMemsetAsync(degU, 0, (size_t)NUx * sizeof(int));
    count_kernel<<<(ETx + 255) / 256, 256>>>(trust_dst, degU, ETx);
    scan_bsums<<<nbU, 256>>>(degU, NUx, bsumU);
    scan_tops<<<1, 64>>>(bsumU, nbU, off_trust + NUx);
    scan_final<<<nbU, 256>>>(degU, NUx, bsumU, off_trust);
    cudaMemsetAsync(curU, 0, (size_t)NUx * sizeof(int));
    scatter_kernel<<<(ETx + 255) / 256, 256>>>(trust_dst, trust_src, ETx,
                                               off_trust, curU, val_trust);

    copy_block<<<(NUx * 64 + 255) / 256, 256>>>(eu, hu_all, HALL, NUx * 64);
    copy_block<<<(NIx * 64 + 255) / 256, 256>>>(ei, hi_all, HALL, NIx * 64);

    for (int l = 0; l < NLAYERS; l++) {
        const float* HU = hu_all + l * 64;        // stride HALL
        float* HUo      = hu_all + (l + 1) * 64;
        const float* HI = hi_all + l * 64;
        float* HIo      = hi_all + (l + 1) * 64;

        const float* rW = rate_W + (size_t)l * 2 * 4096;
        const float* rB = rate_b + (size_t)l * 2 * 64;
        const float* bW = rb_W   + (size_t)l * 2 * 4096;
        const float* bB = rb_b   + (size_t)l * 2 * 64;
        const float* tW = tr_W   + (size_t)l * 2 * 4096;
        const float* tB = tr_b   + (size_t)l * 2 * 64;

        GJobs ju;
        ju.m = 4;
        ju.j[0] = { rW,        rB,        (void*)fsU_rate, 1 };
        ju.j[1] = { bW + 4096, bB + 64,   (void*)fdU_rb,   0 };
        ju.j[2] = { tW,        tB,        (void*)fsU_tr,   1 };
        ju.j[3] = { tW + 4096, tB + 64,   (void*)fdU_tr,   0 };
        gemm64_tc<<<(NUx + 63) / 64, 128>>>(HU, HALL, NUx, ju);

        GJobs ji;
        ji.m = 2;
        ji.j[0] = { rW + 4096, rB + 64,   (void*)fdI_rate, 0 };
        ji.j[1] = { bW,        bB,        (void*)fsI_rb,   1 };
        ji.j[2] = { nullptr, nullptr, nullptr, 0 };
        ji.j[3] = { nullptr, nullptr, nullptr, 0 };
        gemm64_tc<<<(NIx + 63) / 64, 128>>>(HI, HALL, NIx, ji);

        GatJobs gj;
        gj.j[0] = { off_item,  val_item,  fsU_rate, fdI_rate,
                    rate_attn + l * 64, rate_bias + l * 64, HI, HALL, HIo, HALL, NIx };
        gj.j[1] = { off_urate, val_urate, fsI_rb,   fdU_rb,
                    rb_attn + l * 64,   rb_bias + l * 64, nullptr, 0, qbuf, 64, NUx };
        gj.j[2] = { off_trust, val_trust, fsU_tr,   fdU_tr,
                    tr_attn + l * 64,   tr_bias + l * 64, nullptr, 0, pbuf, 64, NUx };
        gj.n0 = NIx; gj.n01 = NIx + NUx; gj.ntot = NIx + 2 * NUx;
        gat_gather3<<<(gj.ntot * 32 + 255) / 256, 256>>>(gj);

        gate_prep<<<1, 256>>>(attW1 + (size_t)l * 2 * 128 * 128,
                              attb1 + (size_t)l * 2 * 128,
                              attW2 + (size_t)l * 2 * 128,
                              attb2 + (size_t)l * 2, gate);
        cudaMemsetAsync(sums, 0, 4 * sizeof(float));
        z_kernel<<<(NUx + 7) / 8, 256>>>(HU, pbuf, qbuf, gate, zinf, zint, sums, NUx);
        gate_apply<<<(NUx + 7) / 8, 256>>>(HU, HUo, pbuf, qbuf, zinf, zint, sums, NUx);
    }

    pair_kernel<<<(EPx + 7) / 8, 256>>>(pos_u, pos_i, hu_all, hi_all, out, EPx);
    pair_kernel<<<(EPx + 7) / 8, 256>>>(neg_u, neg_i, hu_all, hi_all, out + EPx, EPx);
}